// round 9
// baseline (speedup 1.0000x reference)
#include <cuda_runtime.h>

// URPE: out[b,h,i,j] = attention_probs[b,h,i,j] * toe[h,i,j]
// toe[h,i,j] = w[h, L + j - i] if j >= i else w[h, i - j].
//
// B=2, H=16, L=2048. HBM-bound streaming multiply; traffic at its 1.074 GB
// algorithmic floor. Achieved ceiling measured at ~6.73 TB/s (85% of spec).
// R8: identical per-warp body to the best kernel (ILP=4 front-batched
// LDG.128.CS + L2-hot weight gather + STG.128.CS), but THREADS=512 to halve
// CTA count and trim last-wave spread (tail-smoothing, not bandwidth).

static constexpr int LDIM = 2048;
static constexpr int HDIM = 16;
static constexpr int BDIM = 2;
static constexpr int VEC_PER_ROW = LDIM / 4;            // 512 float4 per row
static constexpr long long NVEC =
    (long long)BDIM * HDIM * LDIM * LDIM / 4;           // 33,554,432
static constexpr int THREADS = 512;
static constexpr int ILP = 4;                           // float4s per thread

__global__ __launch_bounds__(THREADS)
void urpe_mul_kernel(const float4* __restrict__ probs,
                     const float*  __restrict__ w,
                     float4*       __restrict__ out) {
    // Block covers ILP*THREADS = 2048 consecutive float4 (4 full rows).
    // Thread t owns vids base + k*512 — each instruction wave is a fully
    // coalesced 8 KB burst.
    const unsigned int base = blockIdx.x * (THREADS * ILP) + threadIdx.x;

    // Phase 1: front-batch all 4 independent stream loads (LDG.128.CS,
    // MLP_p1 = 4 — measured to saturate the DRAM request pipe).
    float4 v[ILP];
#pragma unroll
    for (int k = 0; k < ILP; k++)
        v[k] = __ldcs(&probs[base + k * THREADS]);

    // Phase 2: weight gather (256 KB table, L1/L2-hot), multiply, store.
#pragma unroll
    for (int k = 0; k < ILP; k++) {
        const unsigned int vid = base + k * THREADS;
        const unsigned int j0 = (vid & (VEC_PER_ROW - 1)) << 2;
        const unsigned int i  = (vid >> 9)  & (LDIM - 1);
        const unsigned int h  = (vid >> 20) & (HDIM - 1);
        const float* __restrict__ wh = w + h * (2 * LDIM);

        const int d = (int)j0 - (int)i;
        const int d0 = d,     o0 = (d0 >= 0) ? (LDIM + d0) : -d0;
        const int d1 = d + 1, o1 = (d1 >= 0) ? (LDIM + d1) : -d1;
        const int d2 = d + 2, o2 = (d2 >= 0) ? (LDIM + d2) : -d2;
        const int d3 = d + 3, o3 = (d3 >= 0) ? (LDIM + d3) : -d3;

        v[k].x *= __ldg(wh + o0);
        v[k].y *= __ldg(wh + o1);
        v[k].z *= __ldg(wh + o2);
        v[k].w *= __ldg(wh + o3);

        __stcs(&out[vid], v[k]);
    }
}

extern "C" void kernel_launch(void* const* d_in, const int* in_sizes, int n_in,
                              void* d_out, int out_size) {
    const float4* probs = (const float4*)d_in[0];   // attention_probs [B,H,L,L] f32
    const float*  w     = (const float*)d_in[1];    // urpe_weight_    [H,2L]   f32
    float4*       out   = (float4*)d_out;

    const int blocks = (int)(NVEC / (THREADS * ILP));  // 16384, exact
    urpe_mul_kernel<<<blocks, THREADS>>>(probs, w, out);
}

// round 10
// speedup vs baseline: 1.0006x; 1.0006x over previous
#include <cuda_runtime.h>

// URPE: out[b,h,i,j] = attention_probs[b,h,i,j] * toe[h,i,j]
// toe[h,i,j] = w[h, L + j - i] if j >= i else w[h, i - j].
//
// B=2, H=16, L=2048. HBM-bound streaming multiply; traffic at its 1.074 GB
// algorithmic floor. Ceiling measured at ~6.73 TB/s across 8 kernel shapes.
// R9: same body as the best kernel, but __launch_bounds__(256, 4) relaxes the
// register cap (32 -> ~64) so ptxas can hoist the 16 data-independent weight
// LDGs above the multiplies, front-batching all 20 loads per thread.

static constexpr int LDIM = 2048;
static constexpr int HDIM = 16;
static constexpr int BDIM = 2;
static constexpr int VEC_PER_ROW = LDIM / 4;            // 512 float4 per row
static constexpr long long NVEC =
    (long long)BDIM * HDIM * LDIM * LDIM / 4;           // 33,554,432
static constexpr int THREADS = 256;
static constexpr int ILP = 4;                           // float4s per thread

__global__ __launch_bounds__(THREADS, 4)
void urpe_mul_kernel(const float4* __restrict__ probs,
                     const float*  __restrict__ w,
                     float4*       __restrict__ out) {
    const unsigned int base = blockIdx.x * (THREADS * ILP) + threadIdx.x;

    // Phase 1: front-batch the 4 independent stream loads (LDG.128.CS).
    float4 v[ILP];
#pragma unroll
    for (int k = 0; k < ILP; k++)
        v[k] = __ldcs(&probs[base + k * THREADS]);

    // Phase 2: front-batch ALL 16 weight gathers (addresses are pure index
    // math — independent of the stream loads; extra registers let ptxas
    // keep them hoisted ahead of every FMUL/STG).
    float tw[ILP][4];
#pragma unroll
    for (int k = 0; k < ILP; k++) {
        const unsigned int vid = base + k * THREADS;
        const unsigned int j0 = (vid & (VEC_PER_ROW - 1)) << 2;
        const unsigned int i  = (vid >> 9)  & (LDIM - 1);
        const unsigned int h  = (vid >> 20) & (HDIM - 1);
        const float* __restrict__ wh = w + h * (2 * LDIM);

        const int d = (int)j0 - (int)i;
        const int d0 = d,     o0 = (d0 >= 0) ? (LDIM + d0) : -d0;
        const int d1 = d + 1, o1 = (d1 >= 0) ? (LDIM + d1) : -d1;
        const int d2 = d + 2, o2 = (d2 >= 0) ? (LDIM + d2) : -d2;
        const int d3 = d + 3, o3 = (d3 >= 0) ? (LDIM + d3) : -d3;

        tw[k][0] = __ldg(wh + o0);
        tw[k][1] = __ldg(wh + o1);
        tw[k][2] = __ldg(wh + o2);
        tw[k][3] = __ldg(wh + o3);
    }

    // Phase 3: multiply + streaming stores.
#pragma unroll
    for (int k = 0; k < ILP; k++) {
        v[k].x *= tw[k][0];
        v[k].y *= tw[k][1];
        v[k].z *= tw[k][2];
        v[k].w *= tw[k][3];
        __stcs(&out[base + k * THREADS], v[k]);
    }
}

extern "C" void kernel_launch(void* const* d_in, const int* in_sizes, int n_in,
                              void* d_out, int out_size) {
    const float4* probs = (const float4*)d_in[0];   // attention_probs [B,H,L,L] f32
    const float*  w     = (const float*)d_in[1];    // urpe_weight_    [H,2L]   f32
    float4*       out   = (float4*)d_out;

    const int blocks = (int)(NVEC / (THREADS * ILP));  // 32768, exact
    urpe_mul_kernel<<<blocks, THREADS>>>(probs, w, out);
}